// round 6
// baseline (speedup 1.0000x reference)
#include <cuda_runtime.h>
#include <cuda_bf16.h>
#include <math.h>
#include <stdint.h>

// ============================================================================
// FBP as one dense GEMM (mma.sync path; tcgen05 unavailable in compute_103 PTX)
//   out[pixel, slice] = sum_k G[pixel,k] * F[slice,k],  K = 8 views * 128 det
// Main product in bf16 (m16n8k16); the two low-order cross products in FP8
// e4m3 (m16n8k32, half the instructions), lo-operands pre-scaled by 512 and
// accumulated separately; epilogue combines C + Ccross/512.
// ============================================================================

#define NCHUNK 16                  // K chunks of 64
#define STAGE_B 65536              // Ah16 16K | Bh16 16K | G8 8K | Gl8 8K | F8 8K | Fl8 8K
#define NSTAGE 3
#define GEMM_SMEM (NSTAGE*STAGE_B + 1024)

__device__ float g_h[128];         // ramp filter (circular), scale pi/256 folded
__device__ float g_cosA[128];
__device__ float g_sinA[128];
__device__ float g_wv[128];
__device__ int   g_v0[128];
__device__ int   g_v1[128];

// A operands: [128 ptiles][16 kchunks][...]
__device__ __nv_bfloat16 dGh[16384*1024];   // bf16 hi, 128x64, 128B rows SW128
__device__ unsigned char dG8 [16384*1024];  // e4m3(G),        64B rows SW64
__device__ unsigned char dGl8[16384*1024];  // e4m3(512*(G-Gh))
// B operands: [16 stiles][16 kchunks][...]
__device__ __nv_bfloat16 dFh[2048*1024];
__device__ unsigned char dF8 [2048*1024];
__device__ unsigned char dFl8[2048*1024];

struct Ptrs { const float* p[8]; };

__host__ __device__ __forceinline__ uint32_t swz(uint32_t b) {      // SW128
    return b ^ ((b >> 3) & 0x70);
}

static __device__ __forceinline__ uint32_t bf16x2(float hi, float lo) {
    uint32_t r;
    asm("cvt.rn.bf16x2.f32 %0, %1, %2;" : "=r"(r) : "f"(hi), "f"(lo));
    return r;                                  // low 16 bits = lo
}
static __device__ __forceinline__ unsigned short fp8x2(float hi, float lo) {
    unsigned short r;
    asm("cvt.rn.satfinite.e4m3x2.f32 %0, %1, %2;" : "=h"(r) : "f"(hi), "f"(lo));
    return r;                                  // low byte = lo
}

// ---------------------------------------------------------------------------
__global__ void fbp_setup() {
    int a = threadIdx.x;           // 0..127
    const float PI = 3.14159265358979323846f;

    float th = (float)a * (PI / 128.0f);
    float sn, cs;
    sincosf(th, &sn, &cs);
    g_cosA[a] = cs;
    g_sinA[a] = sn;

    float cv = ((float)a + 0.5f) * (1.0f / 16.0f) - 0.5f;
    cv = fminf(fmaxf(cv, 0.0f), 7.0f);
    int v0 = (int)cv;
    int v1 = v0 + 1; if (v1 > 7) v1 = 7;
    g_v0[a] = v0;
    g_v1[a] = v1;
    g_wv[a] = cv - (float)v0;

    float acc = 0.0f;
    for (int k = 0; k < 128; k++) {
        float ramp = (float)(k < 64 ? k : 128 - k) * (1.0f / 128.0f);
        int ph = (k * a) & 127;
        acc += ramp * cosf((float)ph * (2.0f * PI / 128.0f));
    }
    g_h[a] = acc * (1.0f / 128.0f) * (PI / 256.0f);
}

// ---------------------------------------------------------------------------
// F: ramp-filter (register-window circular conv), split, store all 3 formats.
__global__ __launch_bounds__(128) void fbp_filter(Ptrs P) {
    __shared__ float raws[8][129];
    __shared__ float h2s[256];
    const int tid = threadIdx.x;
    const int s = blockIdx.x;              // slice 0..2047
    h2s[tid] = g_h[tid & 127];
    h2s[tid + 128] = g_h[tid & 127];
    {
        int v = tid >> 4, w0 = (tid & 15) * 8;
        const float* src = P.p[v] + (size_t)s * 128 + w0;
        #pragma unroll
        for (int j = 0; j < 8; j++) raws[v][w0 + j] = src[j];
    }
    __syncthreads();

    const int v  = tid >> 4;
    const int t0 = (tid & 15) * 8;
    float acc[8];
    #pragma unroll
    for (int j = 0; j < 8; j++) acc[j] = 0.0f;
    float hw[8];
    #pragma unroll
    for (int j = 0; j < 8; j++) hw[j] = h2s[t0 + 128 + j];

    #pragma unroll 16
    for (int w = 0; w < 128; w++) {
        float rv = raws[v][w];
        #pragma unroll
        for (int j = 0; j < 8; j++) acc[j] = fmaf(rv, hw[j], acc[j]);
        #pragma unroll
        for (int j = 7; j > 0; j--) hw[j] = hw[j - 1];
        hw[0] = h2s[t0 + 127 - w];
    }

    // split + pack
    uint32_t hb[4];
    float lo[8];
    #pragma unroll
    for (int j = 0; j < 4; j++) {
        hb[j] = bf16x2(acc[2*j+1], acc[2*j]);
        float f0 = __uint_as_float(hb[j] << 16);
        float f1 = __uint_as_float(hb[j] & 0xffff0000u);
        lo[2*j]   = (acc[2*j]   - f0) * 512.0f;
        lo[2*j+1] = (acc[2*j+1] - f1) * 512.0f;
    }
    uint32_t f8a = (uint32_t)fp8x2(acc[1], acc[0]) | ((uint32_t)fp8x2(acc[3], acc[2]) << 16);
    uint32_t f8b = (uint32_t)fp8x2(acc[5], acc[4]) | ((uint32_t)fp8x2(acc[7], acc[6]) << 16);
    uint32_t l8a = (uint32_t)fp8x2(lo[1], lo[0])  | ((uint32_t)fp8x2(lo[3], lo[2])  << 16);
    uint32_t l8b = (uint32_t)fp8x2(lo[5], lo[4])  | ((uint32_t)fp8x2(lo[7], lo[6])  << 16);

    const int r = s & 127, stile = s >> 7;
    int kv0 = v * 128 + t0;
    int kc = kv0 >> 6, c0 = kv0 & 63;
    uint32_t cbase = (uint32_t)(stile * 16 + kc) * 8192u;
    uint32_t ob16 = cbase + (swz((uint32_t)(r * 128 + c0 * 2)) >> 1);
    *(uint4*)(dFh + ob16) = make_uint4(hb[0], hb[1], hb[2], hb[3]);
    uint32_t ob8 = cbase + (((uint32_t)(r * 64 + c0)) ^ ((uint32_t)(r & 6) << 3));
    *(uint2*)(dF8  + ob8) = make_uint2(f8a, f8b);
    *(uint2*)(dFl8 + ob8) = make_uint2(l8a, l8b);
}

// ---------------------------------------------------------------------------
// G: parity-split scatter (conflict-free, deterministic), split, 3 formats.
__global__ __launch_bounds__(128) void fbp_gmat() {
    extern __shared__ float g[];           // 32 * 1024 floats
    __shared__ float shc[128], shs[128], shwv[128];
    __shared__ int shv0[128], shv1[128];
    const int tid = threadIdx.x;
    shc[tid] = g_cosA[tid]; shs[tid] = g_sinA[tid]; shwv[tid] = g_wv[tid];
    shv0[tid] = g_v0[tid];  shv1[tid] = g_v1[tid];
    float4* g4 = (float4*)g;
    #pragma unroll
    for (int i = 0; i < 64; i++) g4[tid + i * 128] = make_float4(0,0,0,0);
    __syncthreads();

    {
        int px = tid >> 2, quad = tid & 3;
        int vp = quad & 1, tp = quad >> 1;
        int p = blockIdx.x * 32 + px;
        float x = (float)(p & 127) - 63.5f;
        float y = (float)(p >> 7)  - 63.5f;
        float* gp = g + px * 1024;
        for (int a = 0; a < 128; a++) {
            float tt = fmaf(y, shs[a], fmaf(x, shc[a], 63.5f));
            tt = fminf(fmaxf(tt, 0.0f), 127.0f);
            int   t0 = (int)tt;
            int   t1 = min(t0 + 1, 127);
            float w1 = tt - (float)t0;
            float w0 = 1.0f - w1;
            float wv = shwv[a];
            int v0 = shv0[a], v1 = shv1[a];
            if ((v0 & 1) == vp) {
                float wvv = 1.0f - wv;
                if ((t0 & 1) == tp) gp[v0 * 128 + t0] += wvv * w0;
                if ((t1 & 1) == tp) gp[v0 * 128 + t1] += wvv * w1;
            }
            if ((v1 & 1) == vp) {
                if ((t0 & 1) == tp) gp[v1 * 128 + t0] += wv * w0;
                if ((t1 & 1) == tp) gp[v1 * 128 + t1] += wv * w1;
            }
        }
    }
    __syncthreads();

    // writeback: units of 8 consecutive k
    for (int u = tid; u < 4096; u += 128) {
        int pl = u >> 7, cu = u & 127;
        int kv0 = cu * 8;
        int kc = kv0 >> 6, c0 = kv0 & 63;
        int p = blockIdx.x * 32 + pl;
        int pt = p >> 7, r = p & 127;
        const float* src = g + pl * 1024 + kv0;
        float val[8];
        #pragma unroll
        for (int j = 0; j < 8; j++) val[j] = src[j];
        uint32_t hb[4]; float lo[8];
        #pragma unroll
        for (int j = 0; j < 4; j++) {
            hb[j] = bf16x2(val[2*j+1], val[2*j]);
            float f0 = __uint_as_float(hb[j] << 16);
            float f1 = __uint_as_float(hb[j] & 0xffff0000u);
            lo[2*j]   = (val[2*j]   - f0) * 512.0f;
            lo[2*j+1] = (val[2*j+1] - f1) * 512.0f;
        }
        uint32_t f8a = (uint32_t)fp8x2(val[1], val[0]) | ((uint32_t)fp8x2(val[3], val[2]) << 16);
        uint32_t f8b = (uint32_t)fp8x2(val[5], val[4]) | ((uint32_t)fp8x2(val[7], val[6]) << 16);
        uint32_t l8a = (uint32_t)fp8x2(lo[1], lo[0])  | ((uint32_t)fp8x2(lo[3], lo[2])  << 16);
        uint32_t l8b = (uint32_t)fp8x2(lo[5], lo[4])  | ((uint32_t)fp8x2(lo[7], lo[6])  << 16);

        uint32_t cbase = (uint32_t)(pt * 16 + kc) * 8192u;
        uint32_t ob16 = cbase + (swz((uint32_t)(r * 128 + c0 * 2)) >> 1);
        *(uint4*)(dGh + ob16) = make_uint4(hb[0], hb[1], hb[2], hb[3]);
        uint32_t ob8 = cbase + (((uint32_t)(r * 64 + c0)) ^ ((uint32_t)(r & 6) << 3));
        *(uint2*)(dG8  + ob8) = make_uint2(f8a, f8b);
        *(uint2*)(dGl8 + ob8) = make_uint2(l8a, l8b);
    }
}

// ---------------------------------------------------------------------------
static __device__ __forceinline__ uint32_t smem_u32(const void* p) {
    uint32_t a;
    asm("{ .reg .u64 t; cvta.to.shared.u64 t, %1; cvt.u32.u64 %0, t; }" : "=r"(a) : "l"(p));
    return a;
}
static __device__ __forceinline__ void cp16(uint32_t dst, const void* src) {
    asm volatile("cp.async.cg.shared.global [%0], [%1], 16;" :: "r"(dst), "l"(src));
}
#define LDSM4(r, addr) \
    asm volatile("ldmatrix.sync.aligned.m8n8.x4.shared.b16 {%0,%1,%2,%3}, [%4];" \
        : "=r"((r)[0]), "=r"((r)[1]), "=r"((r)[2]), "=r"((r)[3]) : "r"(addr))
#define MMA16816(c, a, b0, b1) \
    asm volatile("mma.sync.aligned.m16n8k16.row.col.f32.bf16.bf16.f32 " \
        "{%0,%1,%2,%3}, {%4,%5,%6,%7}, {%8,%9}, {%0,%1,%2,%3};" \
        : "+f"((c)[0]), "+f"((c)[1]), "+f"((c)[2]), "+f"((c)[3]) \
        : "r"((a)[0]), "r"((a)[1]), "r"((a)[2]), "r"((a)[3]), "r"(b0), "r"(b1))
#define MMA16832F8(c, a, b0, b1) \
    asm volatile("mma.sync.aligned.m16n8k32.row.col.f32.e4m3.e4m3.f32 " \
        "{%0,%1,%2,%3}, {%4,%5,%6,%7}, {%8,%9}, {%0,%1,%2,%3};" \
        : "+f"((c)[0]), "+f"((c)[1]), "+f"((c)[2]), "+f"((c)[3]) \
        : "r"((a)[0]), "r"((a)[1]), "r"((a)[2]), "r"((a)[3]), "r"(b0), "r"(b1))

__global__ void __launch_bounds__(256, 1) fbp_gemm(float* __restrict__ out) {
    extern __shared__ unsigned char smraw[];
    const uint32_t sb0 = smem_u32(smraw);
    const uint32_t sb  = (sb0 + 1023u) & ~1023u;
    float* Cp = (float*)(smraw + (sb - sb0));

    const int tid = threadIdx.x, wid = tid >> 5, lane = tid & 31;
    const int stile = blockIdx.x;                  // 0..15  (x fastest -> A shared)
    const int ptile = blockIdx.y;                  // 0..127

    const __nv_bfloat16* gAh = dGh  + (size_t)ptile * 131072;
    const unsigned char* gA8 = dG8  + (size_t)ptile * 131072;
    const unsigned char* gAl = dGl8 + (size_t)ptile * 131072;
    const __nv_bfloat16* gBh = dFh  + (size_t)stile * 131072;
    const unsigned char* gB8 = dF8  + (size_t)stile * 131072;
    const unsigned char* gBl = dFl8 + (size_t)stile * 131072;

    const int mbase = (wid >> 2) * 64;             // 2 M blocks of 64
    const int nbase = (wid & 3) * 32;              // 4 N blocks of 32

    const uint32_t xmask = (uint32_t)(lane & 7) << 4;       // SW128 lane XOR
    const uint32_t xm8   = (uint32_t)(lane & 6) << 3;       // SW64 lane XOR
    const uint32_t arow  = (uint32_t)(lane & 15);
    const uint32_t akoff = (uint32_t)((lane >> 4) << 4);    // bytes
    const uint32_t brow  = (uint32_t)((lane & 7) | ((lane & 16) >> 1));
    const uint32_t bkoff = (uint32_t)((lane & 8) << 1);     // bytes

    float C[4][4][4], Cx[4][4][4];
    #pragma unroll
    for (int i = 0; i < 4; i++)
        #pragma unroll
        for (int j = 0; j < 4; j++)
            #pragma unroll
            for (int q = 0; q < 4; q++) { C[i][j][q] = 0.0f; Cx[i][j][q] = 0.0f; }

    auto copy_chunk = [&](int c) {
        uint32_t st = sb + (uint32_t)(c % NSTAGE) * STAGE_B;
        // 16KB bf16 regions
        #pragma unroll
        for (int p = 0; p < 4; p++) {
            cp16(st +         (uint32_t)(p * 4096 + tid * 16),
                 (const char*)(gAh + c * 8192) + p * 4096 + tid * 16);
            cp16(st + 16384 + (uint32_t)(p * 4096 + tid * 16),
                 (const char*)(gBh + c * 8192) + p * 4096 + tid * 16);
        }
        // 8KB fp8 regions
        #pragma unroll
        for (int p = 0; p < 2; p++) {
            uint32_t o = (uint32_t)(p * 4096 + tid * 16);
            cp16(st + 32768 + o, (const char*)(gA8 + c * 8192) + o);
            cp16(st + 40960 + o, (const char*)(gAl + c * 8192) + o);
            cp16(st + 49152 + o, (const char*)(gB8 + c * 8192) + o);
            cp16(st + 57344 + o, (const char*)(gBl + c * 8192) + o);
        }
        asm volatile("cp.async.commit_group;" ::: "memory");
    };

    copy_chunk(0); copy_chunk(1); copy_chunk(2);

    for (int c = 0; c < NCHUNK; c++) {
        if (c <= NCHUNK - 3)      asm volatile("cp.async.wait_group 2;" ::: "memory");
        else if (c == NCHUNK - 2) asm volatile("cp.async.wait_group 1;" ::: "memory");
        else                      asm volatile("cp.async.wait_group 0;" ::: "memory");
        __syncthreads();

        const uint32_t st = sb + (uint32_t)(c % NSTAGE) * STAGE_B;
        const uint32_t aH = st, bH = st + 16384;
        const uint32_t a8 = st + 32768, al8 = st + 40960;
        const uint32_t b8 = st + 49152, bl8 = st + 57344;

        // ---- main product, bf16 k16 ----
        #pragma unroll
        for (int kk = 0; kk < 4; kk++) {
            const uint32_t kA = ((uint32_t)(kk * 32) + akoff) ^ xmask;
            const uint32_t kB = ((uint32_t)(kk * 32) + bkoff) ^ xmask;
            uint32_t ah[4][4], bh[4][2];
            #pragma unroll
            for (int mt = 0; mt < 4; mt++) {
                uint32_t ro = (uint32_t)(mbase + mt * 16 + arow) * 128u;
                LDSM4(ah[mt], aH + ro + kA);
            }
            #pragma unroll
            for (int h = 0; h < 2; h++) {
                uint32_t ro = (uint32_t)(nbase + h * 16 + brow) * 128u;
                uint32_t rt[4];
                LDSM4(rt, bH + ro + kB);
                bh[2*h][0] = rt[0]; bh[2*h][1] = rt[1];
                bh[2*h+1][0] = rt[2]; bh[2*h+1][1] = rt[3];
            }
            #pragma unroll
            for (int mt = 0; mt < 4; mt++)
                #pragma unroll
                for (int nt = 0; nt < 4; nt++)
                    MMA16816(C[mt][nt], ah[mt], bh[nt][0], bh[nt][1]);
        }

        // ---- cross products, fp8 k32 (x512 scale on lo operands) ----
        #pragma unroll
        for (int s2 = 0; s2 < 2; s2++) {
            const uint32_t kA8 = ((uint32_t)(s2 * 32) + akoff) ^ xm8;
            const uint32_t kB8 = ((uint32_t)(s2 * 32) + bkoff) ^ xm8;
            uint32_t aG[4][4], aL[4][4], bF[4][2], bL[4][2];
            #pragma unroll
            for (int mt = 0; mt < 4; mt++) {
                uint32_t ro = (uint32_t)(mbase + mt * 16 + arow) * 64u;
                LDSM4(aG[mt], a8  + ro + kA8);
                LDSM4(aL[mt], al8 + ro + kA8);
            }
            #pragma unroll
            for (int h = 0; h < 2; h++) {
                uint32_t ro = (uint32_t)(nbase + h * 16 + brow) * 64u;
                uint32_t rt[4];
                LDSM4(rt, b8 + ro + kB8);
                bF[2*h][0] = rt[0]; bF[2*h][1] = rt[1];
                bF[2*h+1][0] = rt[2]; bF[2*h+1][1] = rt[3];
                LDSM4(rt, bl8 + ro + kB8);
                bL[2*h][0] = rt[0]; bL[2*h][1] = rt[1];
                bL[2*h+1][0] = rt[2]; bL[2*h+1][1] = rt[3];
            }
            #pragma unroll
            for (int mt = 0; mt < 4; mt++)
                #pragma unroll
                for (int nt = 0; nt < 4; nt++) {
                    MMA16832F8(Cx[mt][nt], aG[mt], bL[nt][0], bL[nt][1]);  // G * 512*Fl
                    MMA16832F8(Cx[mt][nt], aL[mt], bF[nt][0], bF[nt][1]);  // 512*Gl * F
                }
        }
        __syncthreads();
        if (c + NSTAGE < NCHUNK) copy_chunk(c + NSTAGE);
    }

    // Epilogue: combine + transpose to [slice][pixel] in SMEM, coalesced out.
    __syncthreads();
    #pragma unroll
    for (int mt = 0; mt < 4; mt++)
        #pragma unroll
        for (int nt = 0; nt < 4; nt++) {
            int m0 = mbase + mt * 16 + (lane >> 2);
            int n0 = nbase + nt * 8 + 2 * (lane & 3);
            float v0 = C[mt][nt][0] + Cx[mt][nt][0] * (1.0f/512.0f);
            float v1 = C[mt][nt][1] + Cx[mt][nt][1] * (1.0f/512.0f);
            float v2 = C[mt][nt][2] + Cx[mt][nt][2] * (1.0f/512.0f);
            float v3 = C[mt][nt][3] + Cx[mt][nt][3] * (1.0f/512.0f);
            Cp[(n0    ) * 132 + m0    ] = v0;
            Cp[(n0 + 1) * 132 + m0    ] = v1;
            Cp[(n0    ) * 132 + m0 + 8] = v2;
            Cp[(n0 + 1) * 132 + m0 + 8] = v3;
        }
    __syncthreads();

    const int px = (tid & 31) * 4;
    #pragma unroll
    for (int i = 0; i < 16; i++) {
        int n = (tid >> 5) + i * 8;
        float4 v = *(const float4*)(Cp + n * 132 + px);
        *(float4*)(out + (size_t)(stile * 128 + n) * 16384 + ptile * 128 + px) = v;
    }
}

// ---------------------------------------------------------------------------
extern "C" void kernel_launch(void* const* d_in, const int* in_sizes, int n_in,
                              void* d_out, int out_size) {
    (void)in_sizes; (void)n_in; (void)out_size;
    cudaFuncSetAttribute(fbp_gmat, cudaFuncAttributeMaxDynamicSharedMemorySize, 131072);
    cudaFuncSetAttribute(fbp_gemm, cudaFuncAttributeMaxDynamicSharedMemorySize, GEMM_SMEM);

    fbp_setup<<<1, 128>>>();
    Ptrs P;
    for (int i = 0; i < 8; i++) P.p[i] = (const float*)d_in[i];
    fbp_filter<<<2048, 128>>>(P);
    fbp_gmat<<<512, 128, 131072>>>();
    fbp_gemm<<<dim3(16, 128), 256, GEMM_SMEM>>>((float*)d_out);
}